// round 15
// baseline (speedup 1.0000x reference)
#include <cuda_runtime.h>
#include <cuda_fp16.h>
#include <math.h>
#include <stdint.h>

// Problem constants
#define kB 8
#define kS 2048
#define kD 1024
#define kC 5
#define kM (kB * kS)  // 16384

// ---------------------------------------------------------------------------
// Scratch (device globals)
// ---------------------------------------------------------------------------
__device__ __half g_xh  [(size_t)kM * kD];
__device__ __half g_ctxh[(size_t)kM * kD];
__device__ __half g_bigh[(size_t)kM * 1280];
__device__ __half g_hh  [(size_t)kM * kD];
__device__ float  g_part[(size_t)kB * 64 * kD];
__device__ __half g_wth[(size_t)1280*1024 + (size_t)1024*2048];
__device__ float  g_biasA[1280];

#define WTH_MERGED 0
#define WTH_CD1 ((size_t)1280 * 1024)

// ---------------------------------------------------------------------------
// helpers
// ---------------------------------------------------------------------------
__device__ __forceinline__ uint32_t smem_u32(const void* p) {
    uint32_t a;
    asm("{ .reg .u64 t; cvta.to.shared.u64 t, %1; cvt.u32.u64 %0, t; }"
        : "=r"(a) : "l"(p));
    return a;
}
__device__ __forceinline__ void cp_async16(uint32_t dst, const void* src) {
    asm volatile("cp.async.cg.shared.global [%0], [%1], 16;"
                 :: "r"(dst), "l"(src));
}
__device__ __forceinline__ void cp_commit() {
    asm volatile("cp.async.commit_group;" ::: "memory");
}
template <int N>
__device__ __forceinline__ void cp_wait() {
    asm volatile("cp.async.wait_group %0;" :: "n"(N) : "memory");
}
__device__ __forceinline__ void ldsm_x4(uint32_t* r, uint32_t addr) {
    asm volatile("ldmatrix.sync.aligned.m8n8.x4.shared.b16 {%0,%1,%2,%3}, [%4];"
                 : "=r"(r[0]), "=r"(r[1]), "=r"(r[2]), "=r"(r[3]) : "r"(addr));
}
__device__ __forceinline__ void mma_f16(float* d, const uint32_t* a, const uint32_t* b) {
    asm volatile(
        "mma.sync.aligned.m16n8k16.row.col.f32.f16.f16.f32 "
        "{%0,%1,%2,%3}, {%4,%5,%6,%7}, {%8,%9}, {%0,%1,%2,%3};"
        : "+f"(d[0]), "+f"(d[1]), "+f"(d[2]), "+f"(d[3])
        : "r"(a[0]), "r"(a[1]), "r"(a[2]), "r"(a[3]),
          "r"(b[0]), "r"(b[1]));
}

// Abramowitz–Stegun 7.1.26 erf approximation, |err| <= 1.5e-7
__device__ __forceinline__ float fast_erf(float z) {
    const float az = fabsf(z);
    const float t = __frcp_rn(fmaf(0.3275911f, az, 1.f));
    float p = fmaf(1.061405429f, t, -1.453152027f);
    p = fmaf(p, t, 1.421413741f);
    p = fmaf(p, t, -0.284496736f);
    p = fmaf(p, t, 0.254829592f);
    const float e = __expf(-az * az);
    const float r = 1.f - p * t * e;
    return copysignf(r, z);
}

// ---------------------------------------------------------------------------
// fp16 mma GEMM (one problem per launch), 2 CTAs/SM, 64x64 warp tiles.
//   isG3=1: h = [xh|ctxh] @ Wcd1^T + bcd1   (N=1024, K=2048, grid 1024)
//   isG3=0: big = act(xh @ Wm^T + bm)       (N=1280, K=1024, grid 1280)
// ---------------------------------------------------------------------------
#define BM 128
#define BN 128
#define BK 64
#define LDAH 72
#define ROWB (LDAH * 2)              // 144 bytes
#define NS 3
#define ASZB (BM * ROWB)             // 18432
#define TILEB ((BM + BN) * ROWB)     // 36864
#define SMEM_SZ (NS * TILEB)         // 110592 -> 2 CTAs/SM

__global__ __launch_bounds__(128, 2) void gemm_one(
    const __half* __restrict__ xh, const __half* __restrict__ ctxh,
    const __half* __restrict__ Bt, const float* __restrict__ bias,
    __half* __restrict__ C, int isG3)
{
    extern __shared__ char sm[];
    const uint32_t smb = smem_u32(sm);

    const int tid  = threadIdx.x;
    const int lane = tid & 31;
    const int wid  = tid >> 5;
    const int wm   = wid >> 1;
    const int wn   = wid & 1;

    const int bid = blockIdx.x;
    int brow, bcol;
    if (isG3) { brow = (bid >> 3) * BM; bcol = (bid & 7) * BN; }
    else      { brow = (bid / 10) * BM; bcol = (bid % 10) * BN; }

    const int  N    = isG3 ? 1024 : 1280;
    const int  K1   = 1024;
    const int  K    = isG3 ? 2048 : 1024;
    const int  relu_upto = isG3 ? 0 : 768;
    const int  iters = K / BK;

    const int a_row = wm * 64 + ((lane >> 3) & 1) * 8 + (lane & 7);
    const int a_k   = (lane >> 4) * 8;
    const int b_row = wn * 64 + (lane >> 4) * 8 + (lane & 7);
    const int b_k   = ((lane >> 3) & 1) * 8;

    auto load_tile = [&](int stage, int kt) {
        const uint32_t sbase = smb + (uint32_t)(stage * TILEB);
#pragma unroll
        for (int j = 0; j < 16; j++) {
            const int c = tid + 128 * j;
            const int row = c >> 3;
            const int col = (c & 7) * 8;
            const uint32_t dst = sbase + (uint32_t)(row * ROWB + col * 2);
            const __half* src;
            if (row < BM) {
                src = (kt < K1)
                    ? xh + (size_t)(brow + row) * K1 + kt + col
                    : ctxh + (size_t)(brow + row) * K1 + (kt - K1) + col;
            } else {
                src = Bt + (size_t)(bcol + row - BM) * K + kt + col;
            }
            cp_async16(dst, src);
        }
    };

    float acc[4][8][4];
#pragma unroll
    for (int i = 0; i < 4; i++)
#pragma unroll
        for (int j = 0; j < 8; j++)
#pragma unroll
            for (int q = 0; q < 4; q++) acc[i][j][q] = 0.f;

#pragma unroll
    for (int s = 0; s < NS - 1; s++) {
        load_tile(s, s * BK);
        cp_commit();
    }

    for (int i = 0; i < iters; i++) {
        cp_wait<NS - 2>();
        __syncthreads();
        if (i + NS - 1 < iters) load_tile((i + NS - 1) % NS, (i + NS - 1) * BK);
        cp_commit();

        const uint32_t sa  = smb + (uint32_t)((i % NS) * TILEB);
        const uint32_t sbB = sa + ASZB;

        uint32_t af[2][4][4], bf[2][4][4];
#pragma unroll
        for (int mt = 0; mt < 4; mt++)
            ldsm_x4(af[0][mt], sa + (uint32_t)((a_row + mt * 16) * ROWB + a_k * 2));
#pragma unroll
        for (int np = 0; np < 4; np++)
            ldsm_x4(bf[0][np], sbB + (uint32_t)((b_row + np * 16) * ROWB + b_k * 2));

#pragma unroll
        for (int ks = 0; ks < 4; ks++) {
            const int cur = ks & 1, nxt = cur ^ 1;
            if (ks < 3) {
#pragma unroll
                for (int mt = 0; mt < 4; mt++)
                    ldsm_x4(af[nxt][mt], sa + (uint32_t)((a_row + mt * 16) * ROWB + ((ks + 1) * 16 + a_k) * 2));
#pragma unroll
                for (int np = 0; np < 4; np++)
                    ldsm_x4(bf[nxt][np], sbB + (uint32_t)((b_row + np * 16) * ROWB + ((ks + 1) * 16 + b_k) * 2));
            }
#pragma unroll
            for (int mt = 0; mt < 4; mt++)
#pragma unroll
                for (int nt = 0; nt < 8; nt++)
                    mma_f16(acc[mt][nt], af[cur][mt], &bf[cur][nt >> 1][(nt & 1) * 2]);
        }
    }

    // Epilogue
#pragma unroll
    for (int mt = 0; mt < 4; mt++) {
        const int gr0 = brow + wm * 64 + mt * 16 + (lane >> 2);
#pragma unroll
        for (int h = 0; h < 2; h++) {
            const int row = gr0 + 8 * h;
#pragma unroll
            for (int nt = 0; nt < 8; nt++) {
                const int gc = bcol + wn * 64 + nt * 8 + (lane & 3) * 2;
                float v0 = acc[mt][nt][2 * h]     + bias[gc];
                float v1 = acc[mt][nt][2 * h + 1] + bias[gc + 1];
                if (gc < relu_upto) { v0 = fmaxf(v0, 0.f); v1 = fmaxf(v1, 0.f); }
                *reinterpret_cast<__half2*>(C + (size_t)row * N + gc) =
                    __floats2half2_rn(v0, v1);
            }
        }
    }
}

// ---------------------------------------------------------------------------
// head_all: blocks [0,512)   = fused x copy + fp16 convert + chunk partials
//           blocks [512,3841)= weight transposes (+ bias assembly @3840)
// ---------------------------------------------------------------------------
#define NCH 64
#define CH 32

__global__ __launch_bounds__(256) void head_all(
    const float* __restrict__ x, float* __restrict__ out_x, __half* __restrict__ xh,
    const float* __restrict__ Wcc1, const float* __restrict__ Wbe1,
    const float* __restrict__ Wcr1, const float* __restrict__ Wcd1,
    const float* __restrict__ bcc1, const float* __restrict__ bbe1,
    const float* __restrict__ bcr1,
    __half* __restrict__ wth, float* __restrict__ biasA)
{
    if (blockIdx.x < 512) {
        const int b = blockIdx.x >> 6, ch = blockIdx.x & 63;
        const int d0 = threadIdx.x * 4;
        const size_t base = ((size_t)b * kS + (size_t)ch * CH) * kD + d0;
        float4 s = {0.f, 0.f, 0.f, 0.f};
        for (int t = 0; t < CH; t++) {
            const size_t idx = base + (size_t)t * kD;
            const float4 v = *reinterpret_cast<const float4*>(x + idx);
            *reinterpret_cast<float4*>(out_x + idx) = v;
            __half2* hp = reinterpret_cast<__half2*>(xh + idx);
            hp[0] = __floats2half2_rn(v.x, v.y);
            hp[1] = __floats2half2_rn(v.z, v.w);
            s.x += v.x; s.y += v.y; s.z += v.z; s.w += v.w;
        }
        *reinterpret_cast<float4*>(g_part + ((size_t)b * NCH + ch) * kD + d0) = s;
        return;
    }

    const int t = blockIdx.x - 512;
    if (t == 3328) {
        const int i = threadIdx.x;
        biasA[i]        = bcc1[i];
        biasA[i + 256]  = bcc1[i + 256];
        biasA[i + 512]  = bbe1[i];
        biasA[i + 768]  = bcr1[i];
        biasA[i + 1024] = bcr1[i + 256];
        return;
    }
    __shared__ float tile[32][33];
    const float* W; __half* Wt; int K, N, tn, tk;
    if (t < 512)       { W = Wcc1; Wt = wth;                      K = 1024; N = 512;  int lt = t;        tn = lt % 16; tk = lt / 16; }
    else if (t < 768)  { W = Wbe1; Wt = wth + (size_t)512 * 1024; K = 1024; N = 256;  int lt = t - 512;  tn = lt % 8;  tk = lt / 8;  }
    else if (t < 1280) { W = Wcr1; Wt = wth + (size_t)768 * 1024; K = 1024; N = 512;  int lt = t - 768;  tn = lt % 16; tk = lt / 16; }
    else               { W = Wcd1; Wt = wth + WTH_CD1;            K = 2048; N = 1024; int lt = t - 1280; tn = lt % 32; tk = lt / 32; }

    const int n0 = tn * 32, k0 = tk * 32;
    const int tx = threadIdx.x & 31, ty = threadIdx.x >> 5;
#pragma unroll
    for (int i = ty; i < 32; i += 8)
        tile[i][tx] = W[(size_t)(k0 + i) * N + n0 + tx];
    __syncthreads();
#pragma unroll
    for (int i = ty; i < 32; i += 8)
        Wt[(size_t)(n0 + i) * K + k0 + tx] = __float2half(tile[tx][i]);
}

// ---------------------------------------------------------------------------
// ctx_emit: exclusive scan over chunk partials + in-chunk scan (vectorized)
// ---------------------------------------------------------------------------
__global__ __launch_bounds__(256) void ctx_emit(const __half* __restrict__ xh) {
    const int b = blockIdx.x, ch = blockIdx.y;
    const int d0 = threadIdx.x * 4;
    float pre[4] = {0, 0, 0, 0}, tot[4] = {0, 0, 0, 0};
    for (int c = 0; c < NCH; c++) {
        const float4 p = *reinterpret_cast<const float4*>(
            g_part + ((size_t)b * NCH + c) * kD + d0);
        if (c < ch) { pre[0] += p.x; pre[1] += p.y; pre[2] += p.z; pre[3] += p.w; }
        tot[0] += p.x; tot[1] += p.y; tot[2] += p.z; tot[3] += p.w;
    }
    const float inv_edge = 1.f / (float)(kS - 1);
    const size_t base = ((size_t)b * kS + (size_t)ch * CH) * kD + d0;
    for (int t = 0; t < CH; t++) {
        const int tg = ch * CH + t;
        const bool edge = (tg == 0) || (tg == kS - 1);
        const float ip = edge ? inv_edge : (0.5f / fmaxf((float)tg, 1.f));
        const float is = edge ? inv_edge : (0.5f / fmaxf((float)(kS - 1 - tg), 1.f));
        const size_t idx = base + (size_t)t * kD;
        const __half2* xp = reinterpret_cast<const __half2*>(xh + idx);
        const float2 v01 = __half22float2(xp[0]);
        const float2 v23 = __half22float2(xp[1]);
        float xv[4] = {v01.x, v01.y, v23.x, v23.y};
        float ov[4];
#pragma unroll
        for (int dd = 0; dd < 4; dd++) {
            float prefix = pre[dd];
            pre[dd] += xv[dd];
            float suffix = tot[dd] - pre[dd];
            ov[dd] = prefix * ip + suffix * is;
        }
        __half2* cp = reinterpret_cast<__half2*>(g_ctxh + idx);
        cp[0] = __floats2half2_rn(ov[0], ov[1]);
        cp[1] = __floats2half2_rn(ov[2], ov[3]);
    }
}

// ---------------------------------------------------------------------------
// epilogueA: content softmax -> ct/rel/ctbw*bias -> wb, cred head -> cred.
// warp-per-row, 256 thr = 8 rows.  (depends only on g_bigh)
// ---------------------------------------------------------------------------
__global__ __launch_bounds__(256) void epilogueA(
    const float* __restrict__ Wcc2, const float* __restrict__ bcc2,
    const float* __restrict__ Wbe2, const float* __restrict__ bbe2,
    const float* __restrict__ Wtail, const float* __restrict__ Wcr2,
    const float* __restrict__ bcr2,
    float* __restrict__ out_ct, float* __restrict__ out_wb,
    float* __restrict__ out_rel, float* __restrict__ out_cred)
{
    __shared__ float s_cc2p[256 * 12];
    __shared__ float s_tlp [256 * 12];
    __shared__ float s_be2[256];
    __shared__ float s_cr2[512];

    for (int p = threadIdx.x; p < 256; p += 256) {
#pragma unroll
        for (int q = 0; q < 10; q++)
            s_cc2p[12 * p + q] = Wcc2[10 * p + q];
#pragma unroll
        for (int c = 0; c < 5; c++) {
            s_tlp[12 * p + c]     = Wtail[c * 512 + 2 * p];
            s_tlp[12 * p + 5 + c] = Wtail[c * 512 + 2 * p + 1];
        }
        s_be2[p] = Wbe2[p];
        s_cr2[p] = Wcr2[p];
        s_cr2[p + 256] = Wcr2[p + 256];
    }
    __syncthreads();

    const int w = threadIdx.x >> 5;
    const int l = threadIdx.x & 31;
    const int m = blockIdx.x * 8 + w;

    const __half2* big2 = reinterpret_cast<const __half2*>(g_bigh + (size_t)m * 1280);

    float acc[5] = {0, 0, 0, 0, 0};
#pragma unroll
    for (int i = 0; i < 8; i++) {
        const int p = l + 32 * i;
        const float2 v = __half22float2(big2[p]);
        const float4 w0 = *reinterpret_cast<const float4*>(&s_cc2p[12 * p]);
        const float4 w1 = *reinterpret_cast<const float4*>(&s_cc2p[12 * p + 4]);
        const float2 w2 = *reinterpret_cast<const float2*>(&s_cc2p[12 * p + 8]);
        acc[0] = fmaf(v.x, w0.x, fmaf(v.y, w1.y, acc[0]));
        acc[1] = fmaf(v.x, w0.y, fmaf(v.y, w1.z, acc[1]));
        acc[2] = fmaf(v.x, w0.z, fmaf(v.y, w1.w, acc[2]));
        acc[3] = fmaf(v.x, w0.w, fmaf(v.y, w2.x, acc[3]));
        acc[4] = fmaf(v.x, w1.x, fmaf(v.y, w2.y, acc[4]));
    }
#pragma unroll
    for (int c = 0; c < 5; c++)
#pragma unroll
        for (int o = 16; o; o >>= 1) acc[c] += __shfl_xor_sync(0xffffffffu, acc[c], o);

    float t5[5];
#pragma unroll
    for (int c = 0; c < 5; c++) t5[c] = acc[c] + bcc2[c];
    float mx = t5[0];
#pragma unroll
    for (int c = 1; c < 5; c++) mx = fmaxf(mx, t5[c]);
    float e[5], sum = 0.f;
#pragma unroll
    for (int c = 0; c < 5; c++) { e[c] = __expf(t5[c] - mx); sum += e[c]; }
    const float inv = 1.f / sum;
    float ct[5];
#pragma unroll
    for (int c = 0; c < 5; c++) ct[c] = e[c] * inv;

    if (l < 5) out_ct[(size_t)m * 5 + l] = ct[l];
    if (l == 0) out_rel[m] = 1.f - ct[3];
    const float ctbw = 0.1f * ct[0] + 1.0f * ct[1] + 0.8f * ct[2] + 0.3f * ct[3] + 0.5f * ct[4];

    float ba = 0.f;
#pragma unroll
    for (int i = 0; i < 4; i++) {
        const int j2 = l + 32 * i;
        const float2 v = __half22float2(big2[256 + j2]);
        const float2 wv = *reinterpret_cast<const float2*>(&s_be2[j2 * 2]);
        ba = fmaf(v.x, wv.x, fmaf(v.y, wv.y, ba));
    }
#pragma unroll
    for (int o = 16; o; o >>= 1) ba += __shfl_xor_sync(0xffffffffu, ba, o);
    if (l == 0) {
        float bs = 1.f / (1.f + __expf(-(ba + bbe2[0])));
        out_wb[m] = bs * ctbw;
    }

    float ca = 0.f;
#pragma unroll
    for (int i = 0; i < 8; i++) {
        const int p = l + 32 * i;
        const float2 v = __half22float2(big2[384 + p]);
        const float4 t0 = *reinterpret_cast<const float4*>(&s_tlp[12 * p]);
        const float4 t1 = *reinterpret_cast<const float4*>(&s_tlp[12 * p + 4]);
        const float2 t2 = *reinterpret_cast<const float2*>(&s_tlp[12 * p + 8]);
        float v0 = v.x, v1 = v.y;
        v0 = fmaf(ct[0], t0.x, v0);  v1 = fmaf(ct[0], t1.y, v1);
        v0 = fmaf(ct[1], t0.y, v0);  v1 = fmaf(ct[1], t1.z, v1);
        v0 = fmaf(ct[2], t0.z, v0);  v1 = fmaf(ct[2], t1.w, v1);
        v0 = fmaf(ct[3], t0.w, v0);  v1 = fmaf(ct[3], t2.x, v1);
        v0 = fmaf(ct[4], t1.x, v0);  v1 = fmaf(ct[4], t2.y, v1);
        v0 = fmaxf(v0, 0.f); v1 = fmaxf(v1, 0.f);
        const float2 c2 = *reinterpret_cast<const float2*>(&s_cr2[p * 2]);
        ca = fmaf(v0, c2.x, fmaf(v1, c2.y, ca));
    }
#pragma unroll
    for (int o = 16; o; o >>= 1) ca += __shfl_xor_sync(0xffffffffu, ca, o);
    if (l == 0) out_cred[m] = 1.f / (1.f + __expf(-(ca + bcr2[0])));
}

// ---------------------------------------------------------------------------
// epilogueB: LN + fast_erf GELU + W_cd2 dot + sigmoid -> enhanced
// warp-per-row, 256 thr = 8 rows.  (depends on g_hh and out_ct)
// ---------------------------------------------------------------------------
__global__ __launch_bounds__(256) void epilogueB(
    const float* __restrict__ gln, const float* __restrict__ beln,
    const float* __restrict__ Wcd2, const float* __restrict__ bcd2,
    const float* __restrict__ out_ct, float* __restrict__ out_enh)
{
    __shared__ float s_g[1024], s_b[1024], s_w2[1024];
    for (int i = threadIdx.x; i < 1024; i += 256) {
        s_g[i] = gln[i]; s_b[i] = beln[i]; s_w2[i] = Wcd2[i];
    }
    __syncthreads();

    const int w = threadIdx.x >> 5;
    const int l = threadIdx.x & 31;
    const int m = blockIdx.x * 8 + w;

    const __half2* hh2 = reinterpret_cast<const __half2*>(g_hh + (size_t)m * kD);
    float hv[32];
    float sm1 = 0.f, sq = 0.f;
#pragma unroll
    for (int i = 0; i < 16; i++) {
        const float2 v = __half22float2(hh2[l + 32 * i]);
        hv[2 * i] = v.x; hv[2 * i + 1] = v.y;
        sm1 += v.x + v.y;
        sq  += v.x * v.x + v.y * v.y;
    }
#pragma unroll
    for (int o = 16; o; o >>= 1) {
        sm1 += __shfl_xor_sync(0xffffffffu, sm1, o);
        sq  += __shfl_xor_sync(0xffffffffu, sq,  o);
    }
    const float mu  = sm1 * (1.f / (float)kD);
    const float var = sq * (1.f / (float)kD) - mu * mu;
    const float rstd = rsqrtf(var + 1e-5f);
    const float kInvSqrt2 = 0.70710678118654752f;
    float dot = 0.f;
#pragma unroll
    for (int i = 0; i < 16; i++) {
        const int j = (l + 32 * i) * 2;
        const float2 gv = *reinterpret_cast<const float2*>(&s_g[j]);
        const float2 bv = *reinterpret_cast<const float2*>(&s_b[j]);
        const float2 wv = *reinterpret_cast<const float2*>(&s_w2[j]);
        float y0 = (hv[2 * i]     - mu) * rstd * gv.x + bv.x;
        y0 = 0.5f * y0 * (1.f + fast_erf(y0 * kInvSqrt2));
        dot = fmaf(y0, wv.x, dot);
        float y1 = (hv[2 * i + 1] - mu) * rstd * gv.y + bv.y;
        y1 = 0.5f * y1 * (1.f + fast_erf(y1 * kInvSqrt2));
        dot = fmaf(y1, wv.y, dot);
    }
#pragma unroll
    for (int o = 16; o; o >>= 1) dot += __shfl_xor_sync(0xffffffffu, dot, o);
    if (l == 0) {
        float cont = 1.f / (1.f + __expf(-(dot + bcd2[0])));
        out_enh[m] = fmaxf(cont, out_ct[(size_t)m * 5 + 2]);
    }
}

// ---------------------------------------------------------------------------
// Launch (fork/join stream capture)
// ---------------------------------------------------------------------------
extern "C" void kernel_launch(void* const* d_in, const int* in_sizes, int n_in,
                              void* d_out, int out_size)
{
    (void)in_sizes; (void)n_in; (void)out_size;

    const float* x    = (const float*)d_in[0];
    const float* Wcc1 = (const float*)d_in[1];
    const float* bcc1 = (const float*)d_in[2];
    const float* Wcc2 = (const float*)d_in[3];
    const float* bcc2 = (const float*)d_in[4];
    const float* Wcd1 = (const float*)d_in[5];
    const float* bcd1 = (const float*)d_in[6];
    const float* gln  = (const float*)d_in[7];
    const float* beln = (const float*)d_in[8];
    const float* Wcd2 = (const float*)d_in[9];
    const float* bcd2 = (const float*)d_in[10];
    const float* Wbe1 = (const float*)d_in[11];
    const float* bbe1 = (const float*)d_in[12];
    const float* Wbe2 = (const float*)d_in[13];
    const float* bbe2 = (const float*)d_in[14];
    const float* Wcr1 = (const float*)d_in[15];
    const float* bcr1 = (const float*)d_in[16];
    const float* Wcr2 = (const float*)d_in[17];
    const float* bcr2 = (const float*)d_in[18];

    float* out_x    = (float*)d_out;
    float* out_ct   = out_x + (size_t)kM * kD;
    float* out_enh  = out_ct + (size_t)kM * kC;
    float* out_wb   = out_enh + kM;
    float* out_rel  = out_wb + kM;
    float* out_cred = out_rel + kM;

    __half *xh, *ctxh, *wth, *bigp, *hp;
    float *biasA;
    cudaGetSymbolAddress((void**)&xh,    g_xh);
    cudaGetSymbolAddress((void**)&ctxh,  g_ctxh);
    cudaGetSymbolAddress((void**)&wth,   g_wth);
    cudaGetSymbolAddress((void**)&bigp,  g_bigh);
    cudaGetSymbolAddress((void**)&hp,    g_hh);
    cudaGetSymbolAddress((void**)&biasA, g_biasA);

    static cudaStream_t s1 = nullptr;
    static cudaEvent_t eFork = nullptr, eJoin = nullptr;
    static bool attr_done = false;
    if (!attr_done) {
        cudaFuncSetAttribute(gemm_one, cudaFuncAttributeMaxDynamicSharedMemorySize, SMEM_SZ);
        cudaStreamCreateWithFlags(&s1, cudaStreamNonBlocking);
        cudaEventCreateWithFlags(&eFork, cudaEventDisableTiming);
        cudaEventCreateWithFlags(&eJoin, cudaEventDisableTiming);
        attr_done = true;
    }

    // head: x copy/convert/partials + weight transposes + bias assembly
    head_all<<<3841, 256>>>(x, out_x, xh,
                            Wcc1, Wbe1, Wcr1, Wcd1, bcc1, bbe1, bcr1,
                            wth, biasA);

    // fork: s1 handles ctx -> G3 GEMM
    cudaEventRecord(eFork, 0);
    cudaStreamWaitEvent(s1, eFork, 0);

    ctx_emit<<<dim3(kB, NCH), 256, 0, s1>>>(xh);
    gemm_one<<<1024, 128, SMEM_SZ, s1>>>(xh, ctxh, wth + WTH_CD1, bcd1, hp, 1);
    cudaEventRecord(eJoin, s1);

    // main stream: merged GEMM -> epilogueA (content/bias/cred)
    gemm_one<<<1280, 128, SMEM_SZ, 0>>>(xh, ctxh, wth + WTH_MERGED, biasA, bigp, 0);
    epilogueA<<<kM/8, 256>>>(Wcc2, bcc2, Wbe2, bbe2,
                             Wcr1 + (size_t)1024 * 512, Wcr2, bcr2,
                             out_ct, out_wb, out_rel, out_cred);

    // join, then LN epilogue
    cudaStreamWaitEvent(0, eJoin, 0);
    epilogueB<<<kM/8, 256>>>(gln, beln, Wcd2, bcd2, out_ct, out_enh);
}

// round 16
// speedup vs baseline: 1.0468x; 1.0468x over previous
#include <cuda_runtime.h>
#include <cuda_fp16.h>
#include <math.h>
#include <stdint.h>

// Problem constants
#define kB 8
#define kS 2048
#define kD 1024
#define kC 5
#define kM (kB * kS)  // 16384

// ---------------------------------------------------------------------------
// Scratch (device globals)
// ---------------------------------------------------------------------------
__device__ __half g_xh  [(size_t)kM * kD];
__device__ __half g_ctxh[(size_t)kM * kD];
__device__ __half g_bigh[(size_t)kM * 1280];
__device__ __half g_hh  [(size_t)kM * kD];
__device__ float  g_part[(size_t)kB * 64 * kD];
__device__ float  g_tot [(size_t)kB * kD];
__device__ __half g_wth[(size_t)1280*1024 + (size_t)1024*2048];
__device__ float  g_biasA[1280];

#define WTH_MERGED 0
#define WTH_CD1 ((size_t)1280 * 1024)

// ---------------------------------------------------------------------------
// helpers
// ---------------------------------------------------------------------------
__device__ __forceinline__ uint32_t smem_u32(const void* p) {
    uint32_t a;
    asm("{ .reg .u64 t; cvta.to.shared.u64 t, %1; cvt.u32.u64 %0, t; }"
        : "=r"(a) : "l"(p));
    return a;
}
__device__ __forceinline__ void cp_async16(uint32_t dst, const void* src) {
    asm volatile("cp.async.cg.shared.global [%0], [%1], 16;"
                 :: "r"(dst), "l"(src));
}
__device__ __forceinline__ void cp_commit() {
    asm volatile("cp.async.commit_group;" ::: "memory");
}
template <int N>
__device__ __forceinline__ void cp_wait() {
    asm volatile("cp.async.wait_group %0;" :: "n"(N) : "memory");
}
__device__ __forceinline__ void ldsm_x4(uint32_t* r, uint32_t addr) {
    asm volatile("ldmatrix.sync.aligned.m8n8.x4.shared.b16 {%0,%1,%2,%3}, [%4];"
                 : "=r"(r[0]), "=r"(r[1]), "=r"(r[2]), "=r"(r[3]) : "r"(addr));
}
__device__ __forceinline__ void mma_f16(float* d, const uint32_t* a, const uint32_t* b) {
    asm volatile(
        "mma.sync.aligned.m16n8k16.row.col.f32.f16.f16.f32 "
        "{%0,%1,%2,%3}, {%4,%5,%6,%7}, {%8,%9}, {%0,%1,%2,%3};"
        : "+f"(d[0]), "+f"(d[1]), "+f"(d[2]), "+f"(d[3])
        : "r"(a[0]), "r"(a[1]), "r"(a[2]), "r"(a[3]),
          "r"(b[0]), "r"(b[1]));
}

// Abramowitz–Stegun 7.1.26 erf approximation, |err| <= 1.5e-7
__device__ __forceinline__ float fast_erf(float z) {
    const float az = fabsf(z);
    const float t = __frcp_rn(fmaf(0.3275911f, az, 1.f));
    float p = fmaf(1.061405429f, t, -1.453152027f);
    p = fmaf(p, t, 1.421413741f);
    p = fmaf(p, t, -0.284496736f);
    p = fmaf(p, t, 0.254829592f);
    const float e = __expf(-az * az);
    const float r = 1.f - p * t * e;
    return copysignf(r, z);
}

// ---------------------------------------------------------------------------
// FUSED fp16 mma GEMM, 2 CTAs/SM, 64x64 warp tiles, LPT 1-D grid.
//   bid in [0,1024):    G3   h = [xh|ctxh] @ Wcd1^T + bcd1  (long: 32 iters)
//   bid in [1024,2304): MRG  big = act(xh @ Wm^T + bm)      (short: 16 iters)
// ---------------------------------------------------------------------------
#define BM 128
#define BN 128
#define BK 64
#define LDAH 72
#define ROWB (LDAH * 2)              // 144 bytes
#define NS 3
#define ASZB (BM * ROWB)             // 18432
#define TILEB ((BM + BN) * ROWB)     // 36864
#define SMEM_SZ (NS * TILEB)         // 110592 -> 2 CTAs/SM

__global__ __launch_bounds__(128, 2) void gemm_fused(
    const __half* __restrict__ xh, const __half* __restrict__ ctxh,
    const __half* __restrict__ WtM, const float* __restrict__ biasM,
    const __half* __restrict__ Wt3, const float* __restrict__ bias3,
    __half* __restrict__ outM, __half* __restrict__ out3)
{
    extern __shared__ char sm[];
    const uint32_t smb = smem_u32(sm);

    const int tid  = threadIdx.x;
    const int lane = tid & 31;
    const int wid  = tid >> 5;
    const int wm   = wid >> 1;
    const int wn   = wid & 1;

    const int  bid  = blockIdx.x;
    const bool isG3 = bid < 1024;
    int brow, bcol;
    if (isG3) { brow = (bid >> 3) * BM; bcol = (bid & 7) * BN; }
    else      { const int t = bid - 1024; brow = (t / 10) * BM; bcol = (t % 10) * BN; }

    const int  N    = isG3 ? 1024 : 1280;
    const int  K1   = 1024;
    const int  K    = isG3 ? 2048 : 1024;
    const int  relu_upto = isG3 ? 0 : 768;
    const __half* A2  = ctxh;
    const __half* Bt  = isG3 ? Wt3 : WtM;
    const float*  bias = isG3 ? bias3 : biasM;
    __half* C = isG3 ? out3 : outM;

    const int iters = K / BK;

    const int a_row = wm * 64 + ((lane >> 3) & 1) * 8 + (lane & 7);
    const int a_k   = (lane >> 4) * 8;
    const int b_row = wn * 64 + (lane >> 4) * 8 + (lane & 7);
    const int b_k   = ((lane >> 3) & 1) * 8;

    auto load_tile = [&](int stage, int kt) {
        const uint32_t sbase = smb + (uint32_t)(stage * TILEB);
#pragma unroll
        for (int j = 0; j < 16; j++) {
            const int c = tid + 128 * j;
            const int row = c >> 3;
            const int col = (c & 7) * 8;
            const uint32_t dst = sbase + (uint32_t)(row * ROWB + col * 2);
            const __half* src;
            if (row < BM) {
                src = (kt < K1)
                    ? xh + (size_t)(brow + row) * K1 + kt + col
                    : A2 + (size_t)(brow + row) * K1 + (kt - K1) + col;
            } else {
                src = Bt + (size_t)(bcol + row - BM) * K + kt + col;
            }
            cp_async16(dst, src);
        }
    };

    float acc[4][8][4];
#pragma unroll
    for (int i = 0; i < 4; i++)
#pragma unroll
        for (int j = 0; j < 8; j++)
#pragma unroll
            for (int q = 0; q < 4; q++) acc[i][j][q] = 0.f;

#pragma unroll
    for (int s = 0; s < NS - 1; s++) {
        load_tile(s, s * BK);
        cp_commit();
    }

    for (int i = 0; i < iters; i++) {
        cp_wait<NS - 2>();
        __syncthreads();
        if (i + NS - 1 < iters) load_tile((i + NS - 1) % NS, (i + NS - 1) * BK);
        cp_commit();

        const uint32_t sa  = smb + (uint32_t)((i % NS) * TILEB);
        const uint32_t sbB = sa + ASZB;

        uint32_t af[2][4][4], bf[2][4][4];
#pragma unroll
        for (int mt = 0; mt < 4; mt++)
            ldsm_x4(af[0][mt], sa + (uint32_t)((a_row + mt * 16) * ROWB + a_k * 2));
#pragma unroll
        for (int np = 0; np < 4; np++)
            ldsm_x4(bf[0][np], sbB + (uint32_t)((b_row + np * 16) * ROWB + b_k * 2));

#pragma unroll
        for (int ks = 0; ks < 4; ks++) {
            const int cur = ks & 1, nxt = cur ^ 1;
            if (ks < 3) {
#pragma unroll
                for (int mt = 0; mt < 4; mt++)
                    ldsm_x4(af[nxt][mt], sa + (uint32_t)((a_row + mt * 16) * ROWB + ((ks + 1) * 16 + a_k) * 2));
#pragma unroll
                for (int np = 0; np < 4; np++)
                    ldsm_x4(bf[nxt][np], sbB + (uint32_t)((b_row + np * 16) * ROWB + ((ks + 1) * 16 + b_k) * 2));
            }
#pragma unroll
            for (int mt = 0; mt < 4; mt++)
#pragma unroll
                for (int nt = 0; nt < 8; nt++)
                    mma_f16(acc[mt][nt], af[cur][mt], &bf[cur][nt >> 1][(nt & 1) * 2]);
        }
    }

    // Epilogue
#pragma unroll
    for (int mt = 0; mt < 4; mt++) {
        const int gr0 = brow + wm * 64 + mt * 16 + (lane >> 2);
#pragma unroll
        for (int h = 0; h < 2; h++) {
            const int row = gr0 + 8 * h;
#pragma unroll
            for (int nt = 0; nt < 8; nt++) {
                const int gc = bcol + wn * 64 + nt * 8 + (lane & 3) * 2;
                float v0 = acc[mt][nt][2 * h]     + bias[gc];
                float v1 = acc[mt][nt][2 * h + 1] + bias[gc + 1];
                if (gc < relu_upto) { v0 = fmaxf(v0, 0.f); v1 = fmaxf(v1, 0.f); }
                *reinterpret_cast<__half2*>(C + (size_t)row * N + gc) =
                    __floats2half2_rn(v0, v1);
            }
        }
    }
}

// ---------------------------------------------------------------------------
// head_all: blocks [0,512)   = fused x copy + fp16 convert + chunk partials
//           blocks [512,3841)= weight transposes (+ bias assembly @3840)
// ---------------------------------------------------------------------------
#define NCH 64
#define CH 32

__global__ __launch_bounds__(256) void head_all(
    const float* __restrict__ x, float* __restrict__ out_x, __half* __restrict__ xh,
    const float* __restrict__ Wcc1, const float* __restrict__ Wbe1,
    const float* __restrict__ Wcr1, const float* __restrict__ Wcd1,
    const float* __restrict__ bcc1, const float* __restrict__ bbe1,
    const float* __restrict__ bcr1,
    __half* __restrict__ wth, float* __restrict__ biasA)
{
    if (blockIdx.x < 512) {
        const int b = blockIdx.x >> 6, ch = blockIdx.x & 63;
        const int d0 = threadIdx.x * 4;
        const size_t base = ((size_t)b * kS + (size_t)ch * CH) * kD + d0;
        float4 s = {0.f, 0.f, 0.f, 0.f};
        for (int t = 0; t < CH; t++) {
            const size_t idx = base + (size_t)t * kD;
            const float4 v = *reinterpret_cast<const float4*>(x + idx);
            *reinterpret_cast<float4*>(out_x + idx) = v;
            __half2* hp = reinterpret_cast<__half2*>(xh + idx);
            hp[0] = __floats2half2_rn(v.x, v.y);
            hp[1] = __floats2half2_rn(v.z, v.w);
            s.x += v.x; s.y += v.y; s.z += v.z; s.w += v.w;
        }
        *reinterpret_cast<float4*>(g_part + ((size_t)b * NCH + ch) * kD + d0) = s;
        return;
    }

    const int t = blockIdx.x - 512;
    if (t == 3328) {
        const int i = threadIdx.x;
        biasA[i]        = bcc1[i];
        biasA[i + 256]  = bcc1[i + 256];
        biasA[i + 512]  = bbe1[i];
        biasA[i + 768]  = bcr1[i];
        biasA[i + 1024] = bcr1[i + 256];
        return;
    }
    __shared__ float tile[32][33];
    const float* W; __half* Wt; int K, N, tn, tk;
    if (t < 512)       { W = Wcc1; Wt = wth;                      K = 1024; N = 512;  int lt = t;        tn = lt % 16; tk = lt / 16; }
    else if (t < 768)  { W = Wbe1; Wt = wth + (size_t)512 * 1024; K = 1024; N = 256;  int lt = t - 512;  tn = lt % 8;  tk = lt / 8;  }
    else if (t < 1280) { W = Wcr1; Wt = wth + (size_t)768 * 1024; K = 1024; N = 512;  int lt = t - 768;  tn = lt % 16; tk = lt / 16; }
    else               { W = Wcd1; Wt = wth + WTH_CD1;            K = 2048; N = 1024; int lt = t - 1280; tn = lt % 32; tk = lt / 32; }

    const int n0 = tn * 32, k0 = tk * 32;
    const int tx = threadIdx.x & 31, ty = threadIdx.x >> 5;
#pragma unroll
    for (int i = ty; i < 32; i += 8)
        tile[i][tx] = W[(size_t)(k0 + i) * N + n0 + tx];
    __syncthreads();
#pragma unroll
    for (int i = ty; i < 32; i += 8)
        Wt[(size_t)(n0 + i) * K + k0 + tx] = __float2half(tile[tx][i]);
}

// ---------------------------------------------------------------------------
// ctx_scan: convert g_part to EXCLUSIVE chunk prefixes in place; totals -> g_tot.
// One thread per (b, d). Same serial add order as the old ctx_emit loop.
// ---------------------------------------------------------------------------
__global__ __launch_bounds__(256) void ctx_scan() {
    const int b = blockIdx.x;
    const int d = blockIdx.y * 256 + threadIdx.x;
    float run = 0.f;
    for (int c = 0; c < NCH; c++) {
        float* p = g_part + ((size_t)b * NCH + c) * kD + d;
        const float v = *p;
        *p = run;         // exclusive prefix
        run += v;
    }
    g_tot[(size_t)b * kD + d] = run;
}

// ---------------------------------------------------------------------------
// ctx_emit: reads its own exclusive chunk prefix + total, scans its chunk.
// ---------------------------------------------------------------------------
__global__ __launch_bounds__(256) void ctx_emit(const __half* __restrict__ xh) {
    const int b = blockIdx.x, ch = blockIdx.y;
    const int d0 = threadIdx.x * 4;
    const float4 pr = *reinterpret_cast<const float4*>(
        g_part + ((size_t)b * NCH + ch) * kD + d0);
    const float4 tt = *reinterpret_cast<const float4*>(
        g_tot + (size_t)b * kD + d0);
    float pre[4] = {pr.x, pr.y, pr.z, pr.w};
    float tot[4] = {tt.x, tt.y, tt.z, tt.w};

    const float inv_edge = 1.f / (float)(kS - 1);
    const size_t base = ((size_t)b * kS + (size_t)ch * CH) * kD + d0;
    for (int t = 0; t < CH; t++) {
        const int tg = ch * CH + t;
        const bool edge = (tg == 0) || (tg == kS - 1);
        const float ip = edge ? inv_edge : (0.5f / fmaxf((float)tg, 1.f));
        const float is = edge ? inv_edge : (0.5f / fmaxf((float)(kS - 1 - tg), 1.f));
        const size_t idx = base + (size_t)t * kD;
        const __half2* xp = reinterpret_cast<const __half2*>(xh + idx);
        const float2 v01 = __half22float2(xp[0]);
        const float2 v23 = __half22float2(xp[1]);
        float xv[4] = {v01.x, v01.y, v23.x, v23.y};
        float ov[4];
#pragma unroll
        for (int dd = 0; dd < 4; dd++) {
            float prefix = pre[dd];
            pre[dd] += xv[dd];
            float suffix = tot[dd] - pre[dd];
            ov[dd] = prefix * ip + suffix * is;
        }
        __half2* cp = reinterpret_cast<__half2*>(g_ctxh + idx);
        cp[0] = __floats2half2_rn(ov[0], ov[1]);
        cp[1] = __floats2half2_rn(ov[2], ov[3]);
    }
}

// ---------------------------------------------------------------------------
// MEGA epilogue: 2 warps/row task-split, fast_erf + __expf transcendentals.
// ---------------------------------------------------------------------------
__global__ __launch_bounds__(512) void epilogue_kernel(
    const float* __restrict__ Wcc2, const float* __restrict__ bcc2,
    const float* __restrict__ Wbe2, const float* __restrict__ bbe2,
    const float* __restrict__ Wtail, const float* __restrict__ Wcr2,
    const float* __restrict__ bcr2,
    const float* __restrict__ gln, const float* __restrict__ beln,
    const float* __restrict__ Wcd2, const float* __restrict__ bcd2,
    float* __restrict__ out_ct, float* __restrict__ out_enh,
    float* __restrict__ out_wb, float* __restrict__ out_rel,
    float* __restrict__ out_cred)
{
    __shared__ float s_cc2p[256 * 12];
    __shared__ float s_tlp [256 * 12];
    __shared__ float s_be2[256];
    __shared__ float s_cr2[512];
    __shared__ float s_g[1024], s_b[1024], s_w2[1024];
    __shared__ float s_ct2[8];

    for (int p = threadIdx.x; p < 256; p += 512) {
#pragma unroll
        for (int q = 0; q < 10; q++)
            s_cc2p[12 * p + q] = Wcc2[10 * p + q];
#pragma unroll
        for (int c = 0; c < 5; c++) {
            s_tlp[12 * p + c]     = Wtail[c * 512 + 2 * p];
            s_tlp[12 * p + 5 + c] = Wtail[c * 512 + 2 * p + 1];
        }
    }
    for (int i = threadIdx.x; i < 256; i += 512) s_be2[i] = Wbe2[i];
    for (int i = threadIdx.x; i < 512; i += 512) s_cr2[i] = Wcr2[i];
    for (int i = threadIdx.x; i < 1024; i += 512) {
        s_g[i] = gln[i]; s_b[i] = beln[i]; s_w2[i] = Wcd2[i];
    }
    __syncthreads();

    const int w    = threadIdx.x >> 5;
    const int l    = threadIdx.x & 31;
    const int row  = w >> 1;
    const int task = w & 1;
    const int m    = blockIdx.x * 8 + row;

    float cont = 0.f;

    if (task == 0) {
        const __half2* big2 = reinterpret_cast<const __half2*>(g_bigh + (size_t)m * 1280);

        float acc[5] = {0, 0, 0, 0, 0};
#pragma unroll
        for (int i = 0; i < 8; i++) {
            const int p = l + 32 * i;
            const float2 v = __half22float2(big2[p]);
            const float4 w0 = *reinterpret_cast<const float4*>(&s_cc2p[12 * p]);
            const float4 w1 = *reinterpret_cast<const float4*>(&s_cc2p[12 * p + 4]);
            const float2 w2 = *reinterpret_cast<const float2*>(&s_cc2p[12 * p + 8]);
            acc[0] = fmaf(v.x, w0.x, fmaf(v.y, w1.y, acc[0]));
            acc[1] = fmaf(v.x, w0.y, fmaf(v.y, w1.z, acc[1]));
            acc[2] = fmaf(v.x, w0.z, fmaf(v.y, w1.w, acc[2]));
            acc[3] = fmaf(v.x, w0.w, fmaf(v.y, w2.x, acc[3]));
            acc[4] = fmaf(v.x, w1.x, fmaf(v.y, w2.y, acc[4]));
        }
#pragma unroll
        for (int c = 0; c < 5; c++)
#pragma unroll
            for (int o = 16; o; o >>= 1) acc[c] += __shfl_xor_sync(0xffffffffu, acc[c], o);

        float t5[5];
#pragma unroll
        for (int c = 0; c < 5; c++) t5[c] = acc[c] + bcc2[c];
        float mx = t5[0];
#pragma unroll
        for (int c = 1; c < 5; c++) mx = fmaxf(mx, t5[c]);
        float e[5], sum = 0.f;
#pragma unroll
        for (int c = 0; c < 5; c++) { e[c] = __expf(t5[c] - mx); sum += e[c]; }
        const float inv = 1.f / sum;
        float ct[5];
#pragma unroll
        for (int c = 0; c < 5; c++) ct[c] = e[c] * inv;

        if (l < 5) out_ct[(size_t)m * 5 + l] = ct[l];
        if (l == 0) { out_rel[m] = 1.f - ct[3]; s_ct2[row] = ct[2]; }
        const float ctbw = 0.1f * ct[0] + 1.0f * ct[1] + 0.8f * ct[2] + 0.3f * ct[3] + 0.5f * ct[4];

        float ba = 0.f;
#pragma unroll
        for (int i = 0; i < 4; i++) {
            const int j2 = l + 32 * i;
            const float2 v = __half22float2(big2[256 + j2]);
            const float2 wv = *reinterpret_cast<const float2*>(&s_be2[j2 * 2]);
            ba = fmaf(v.x, wv.x, fmaf(v.y, wv.y, ba));
        }
#pragma unroll
        for (int o = 16; o; o >>= 1) ba += __shfl_xor_sync(0xffffffffu, ba, o);
        if (l == 0) {
            float bs = 1.f / (1.f + __expf(-(ba + bbe2[0])));
            out_wb[m] = bs * ctbw;
        }

        float ca = 0.f;
#pragma unroll
        for (int i = 0; i < 8; i++) {
            const int p = l + 32 * i;
            const float2 v = __half22float2(big2[384 + p]);
            const float4 t0 = *reinterpret_cast<const float4*>(&s_tlp[12 * p]);
            const float4 t1 = *reinterpret_cast<const float4*>(&s_tlp[12 * p + 4]);
            const float2 t2 = *reinterpret_cast<const float2*>(&s_tlp[12 * p + 8]);
            float v0 = v.x, v1 = v.y;
            v0 = fmaf(ct[0], t0.x, v0);  v1 = fmaf(ct[0], t1.y, v1);
            v0 = fmaf(ct[1], t0.y, v0);  v1 = fmaf(ct[1], t1.z, v1);
            v0 = fmaf(ct[2], t0.z, v0);  v1 = fmaf(ct[2], t1.w, v1);
            v0 = fmaf(ct[3], t0.w, v0);  v1 = fmaf(ct[3], t2.x, v1);
            v0 = fmaf(ct[4], t1.x, v0);  v1 = fmaf(ct[4], t2.y, v1);
            v0 = fmaxf(v0, 0.f); v1 = fmaxf(v1, 0.f);
            const float2 c2 = *reinterpret_cast<const float2*>(&s_cr2[p * 2]);
            ca = fmaf(v0, c2.x, fmaf(v1, c2.y, ca));
        }
#pragma unroll
        for (int o = 16; o; o >>= 1) ca += __shfl_xor_sync(0xffffffffu, ca, o);
        if (l == 0) out_cred[m] = 1.f / (1.f + __expf(-(ca + bcr2[0])));
    } else {
        const __half2* hh2 = reinterpret_cast<const __half2*>(g_hh + (size_t)m * kD);
        float hv[32];
        float sm1 = 0.f, sq = 0.f;
#pragma unroll
        for (int i = 0; i < 16; i++) {
            const float2 v = __half22float2(hh2[l + 32 * i]);
            hv[2 * i] = v.x; hv[2 * i + 1] = v.y;
            sm1 += v.x + v.y;
            sq  += v.x * v.x + v.y * v.y;
        }
#pragma unroll
        for (int o = 16; o; o >>= 1) {
            sm1 += __shfl_xor_sync(0xffffffffu, sm1, o);
            sq  += __shfl_xor_sync(0xffffffffu, sq,  o);
        }
        const float mu  = sm1 * (1.f / (float)kD);
        const float var = sq * (1.f / (float)kD) - mu * mu;
        const float rstd = rsqrtf(var + 1e-5f);
        const float kInvSqrt2 = 0.70710678118654752f;
        float dot = 0.f;
#pragma unroll
        for (int i = 0; i < 16; i++) {
            const int j = (l + 32 * i) * 2;
            const float2 gv = *reinterpret_cast<const float2*>(&s_g[j]);
            const float2 bv = *reinterpret_cast<const float2*>(&s_b[j]);
            const float2 wv = *reinterpret_cast<const float2*>(&s_w2[j]);
            float y0 = (hv[2 * i]     - mu) * rstd * gv.x + bv.x;
            y0 = 0.5f * y0 * (1.f + fast_erf(y0 * kInvSqrt2));
            dot = fmaf(y0, wv.x, dot);
            float y1 = (hv[2 * i + 1] - mu) * rstd * gv.y + bv.y;
            y1 = 0.5f * y1 * (1.f + fast_erf(y1 * kInvSqrt2));
            dot = fmaf(y1, wv.y, dot);
        }
#pragma unroll
        for (int o = 16; o; o >>= 1) dot += __shfl_xor_sync(0xffffffffu, dot, o);
        cont = 1.f / (1.f + __expf(-(dot + bcd2[0])));
    }

    __syncthreads();
    if (task == 1 && l == 0)
        out_enh[m] = fmaxf(cont, s_ct2[row]);
}

// ---------------------------------------------------------------------------
// Launch
// ---------------------------------------------------------------------------
extern "C" void kernel_launch(void* const* d_in, const int* in_sizes, int n_in,
                              void* d_out, int out_size)
{
    (void)in_sizes; (void)n_in; (void)out_size;

    const float* x    = (const float*)d_in[0];
    const float* Wcc1 = (const float*)d_in[1];
    const float* bcc1 = (const float*)d_in[2];
    const float* Wcc2 = (const float*)d_in[3];
    const float* bcc2 = (const float*)d_in[4];
    const float* Wcd1 = (const float*)d_in[5];
    const float* bcd1 = (const float*)d_in[6];
    const float* gln  = (const float*)d_in[7];
    const float* beln = (const float*)d_in[8];
    const float* Wcd2 = (const float*)d_in[9];
    const float* bcd2 = (const float*)d_in[10];
    const float* Wbe1 = (const float*)d_in[11];
    const float* bbe1 = (const float*)d_in[12];
    const float* Wbe2 = (const float*)d_in[13];
    const float* bbe2 = (const float*)d_in[14];
    const float* Wcr1 = (const float*)d_in[15];
    const float* bcr1 = (const float*)d_in[16];
    const float* Wcr2 = (const float*)d_in[17];
    const float* bcr2 = (const float*)d_in[18];

    float* out_x    = (float*)d_out;
    float* out_ct   = out_x + (size_t)kM * kD;
    float* out_enh  = out_ct + (size_t)kM * kC;
    float* out_wb   = out_enh + kM;
    float* out_rel  = out_wb + kM;
    float* out_cred = out_rel + kM;

    __half *xh, *ctxh, *wth, *bigp, *hp;
    float *biasA;
    cudaGetSymbolAddress((void**)&xh,    g_xh);
    cudaGetSymbolAddress((void**)&ctxh,  g_ctxh);
    cudaGetSymbolAddress((void**)&wth,   g_wth);
    cudaGetSymbolAddress((void**)&bigp,  g_bigh);
    cudaGetSymbolAddress((void**)&hp,    g_hh);
    cudaGetSymbolAddress((void**)&biasA, g_biasA);

    cudaFuncSetAttribute(gemm_fused, cudaFuncAttributeMaxDynamicSharedMemorySize, SMEM_SZ);

    // fused head: x copy/convert/partials (blocks 0..511) + transposes (512..3840)
    head_all<<<3841, 256>>>(x, out_x, xh,
                            Wcc1, Wbe1, Wcr1, Wcd1, bcc1, bbe1, bcr1,
                            wth, biasA);

    // chunk-prefix scan, then ctx emit (reads only own prefix + total)
    ctx_scan<<<dim3(kB, kD / 256), 256>>>();
    ctx_emit<<<dim3(kB, NCH), 256>>>(xh);

    // ONE fused GEMM launch, LPT order (long G3 CTAs first), 2 CTAs/SM
    gemm_fused<<<2304, 128, SMEM_SZ>>>(
        xh, ctxh,
        wth + WTH_MERGED, biasA,
        wth + WTH_CD1, bcd1,
        bigp, hp);

    // mega epilogue (2 warps/row, task-split, fast transcendentals)
    epilogue_kernel<<<kM/8, 512>>>(
        Wcc2, bcc2, Wbe2, bbe2,
        Wcr1 + (size_t)1024 * 512, Wcr2, bcr2,
        gln, beln, Wcd2, bcd2,
        out_ct, out_enh, out_wb, out_rel, out_cred);
}